// round 14
// baseline (speedup 1.0000x reference)
#include <cuda_runtime.h>
#include <cstdint>

#define OUT_F 16

// ---------------------------------------------------------------------------
// Scatter-add, quad layout (4 threads per edge, one float4 chunk each) with
// 2-way ILP: thread handles quad-elements t and t+half; all 4 loads issued
// before the 2 REDs. One-shot grid with 128-thread CTAs: CTA replacement is
// the software pipeline (fresh CTAs begin with loads); smaller CTAs halve
// the retire-drain granularity vs 256. LTS atomic ALU binds (~48us floor:
// 12.8M RED.128 lane-ops x ~1.29cyc / 184 slices). red.v4.f32 is the widest
// reduction sm_103a supports (v8 rejected by ptxas).
// Exact variant: work == 2*half, no predication.
// ---------------------------------------------------------------------------
__global__ void __launch_bounds__(128)
scatter_add_quad2_exact(const int* __restrict__ src,
                        const float4* __restrict__ w,   // edge_w as [4E] float4
                        float* __restrict__ out,        // [N][16]
                        int half)                       // work/2, mult of 32
{
    int t = blockIdx.x * blockDim.x + threadIdx.x;
    if (t >= half) return;
    int t2 = t + half;

    int s1 = __ldg(src + (t  >> 2));
    int s2 = __ldg(src + (t2 >> 2));
    float4 v1 = __ldcs(w + t);
    float4 v2 = __ldcs(w + t2);

    float* d1 = out + (size_t)s1 * OUT_F + (t  & 3) * 4;
    float* d2 = out + (size_t)s2 * OUT_F + (t2 & 3) * 4;
    asm volatile("red.global.add.v4.f32 [%0], {%1,%2,%3,%4};"
                 :: "l"(d1), "f"(v1.x), "f"(v1.y), "f"(v1.z), "f"(v1.w) : "memory");
    asm volatile("red.global.add.v4.f32 [%0], {%1,%2,%3,%4};"
                 :: "l"(d2), "f"(v2.x), "f"(v2.y), "f"(v2.z), "f"(v2.w) : "memory");
}

// General variant (guarded second stream) for shapes where work is not an
// exact multiple of 64.
__global__ void __launch_bounds__(128)
scatter_add_quad2(const int* __restrict__ src,
                  const float4* __restrict__ w,
                  float* __restrict__ out,
                  int work,                        // 4*E
                  int half)                        // >= work/2, mult of 32
{
    int t = blockIdx.x * blockDim.x + threadIdx.x;
    if (t >= half) return;
    int t2 = t + half;
    bool p2 = (t2 < work);

    int s1 = __ldg(src + (t >> 2));
    float4 v1 = __ldcs(w + t);
    int s2 = p2 ? __ldg(src + (t2 >> 2)) : 0;
    float4 v2 = p2 ? __ldcs(w + t2) : make_float4(0.f, 0.f, 0.f, 0.f);

    float* d1 = out + (size_t)s1 * OUT_F + (t & 3) * 4;
    asm volatile("red.global.add.v4.f32 [%0], {%1,%2,%3,%4};"
                 :: "l"(d1), "f"(v1.x), "f"(v1.y), "f"(v1.z), "f"(v1.w) : "memory");
    if (p2) {
        float* d2 = out + (size_t)s2 * OUT_F + (t2 & 3) * 4;
        asm volatile("red.global.add.v4.f32 [%0], {%1,%2,%3,%4};"
                     :: "l"(d2), "f"(v2.x), "f"(v2.y), "f"(v2.z), "f"(v2.w) : "memory");
    }
}

// ---------------------------------------------------------------------------
// kernel_launch
// Inputs (metadata order): edge [2, E] int32, edge_w [E, 16] f32, N, E, F
// Zero via memset graph node (cheapest measured).
// ---------------------------------------------------------------------------
extern "C" void kernel_launch(void* const* d_in, const int* in_sizes, int n_in,
                              void* d_out, int out_size) {
    const int*    edge   = (const int*)d_in[0];      // [2, E]; row 0 = src
    const float4* edge_w = (const float4*)d_in[1];   // [E, 16] -> [4E] float4
    float*        out    = (float*)d_out;            // [N, 16]

    const int E    = in_sizes[0] / 2;                // edge has 2*E elements
    const int work = 4 * E;                          // quad elements

    cudaMemsetAsync(d_out, 0, (size_t)out_size * sizeof(float));

    const int threads = 128;
    if ((work & 63) == 0) {
        int half = work / 2;                         // multiple of 32
        int blocks = (half + threads - 1) / threads; // 50000 for E=3.2M
        scatter_add_quad2_exact<<<blocks, threads>>>(edge, edge_w, out, half);
    } else {
        int half = (work + 1) / 2;
        half = (half + 31) & ~31;
        int blocks = (half + threads - 1) / threads;
        scatter_add_quad2<<<blocks, threads>>>(edge, edge_w, out, work, half);
    }
}